// round 16
// baseline (speedup 1.0000x reference)
#include <cuda_runtime.h>
#include <cuda_bf16.h>
#include <math.h>

// Problem dims
#define SLEN 1024
#define BSZ  32
#define NH   16
#define DH   64
#define INDIM 1024            // NH*DH
#define MROWS (SLEN*BSZ)      // 32768

typedef unsigned long long u64;

// Scratch (device globals; no allocation allowed)
__device__ __nv_bfloat16 g_ys_bf[(size_t)MROWS * INDIM];   // scan output, bf16
__device__ __nv_bfloat16 g_wb16[(size_t)INDIM * INDIM];    // out_w in bf16
__device__ float g_mu[MROWS];
__device__ float g_rstd[MROWS];

// ---------------------------------------------------------------------------
// packed f32x2 helpers
// ---------------------------------------------------------------------------
__device__ __forceinline__ u64 pack2(float lo, float hi) {
  u64 r; asm("mov.b64 %0, {%1, %2};" : "=l"(r) : "f"(lo), "f"(hi)); return r;
}
__device__ __forceinline__ void unpack2(u64 v, float& lo, float& hi) {
  asm("mov.b64 {%0, %1}, %2;" : "=f"(lo), "=f"(hi) : "l"(v));
}
__device__ __forceinline__ u64 fma2(u64 a, u64 b, u64 c) {
  u64 d; asm("fma.rn.f32x2 %0, %1, %2, %3;" : "=l"(d) : "l"(a), "l"(b), "l"(c));
  return d;
}

// ---------------------------------------------------------------------------
// 64-thread (2-warp) SUM reduction, N values, ONE barrier (shfl butterfly;
// redux.f32 is NOT supported on sm_103 — integer only).
// ---------------------------------------------------------------------------
template<int N>
__device__ __forceinline__ void reduce64_sum(float* v, float* red, int warp, int lane) {
  #pragma unroll
  for (int off = 16; off > 0; off >>= 1) {
    #pragma unroll
    for (int i = 0; i < N; i++)
      v[i] += __shfl_xor_sync(0xffffffffu, v[i], off);
  }
  if (lane == 0) {
    #pragma unroll
    for (int i = 0; i < N; i++) red[warp * N + i] = v[i];
  }
  __syncthreads();
  #pragma unroll
  for (int i = 0; i < N; i++)
    v[i] = red[i] + red[N + i];
}

// ---------------------------------------------------------------------------
// SRWM sequential scan (512 CTAs x 64 threads) — R9 structure with ONE change:
// x_{t+1} is published into the SAME x_s buffer after the reduce barrier
// (x_s is dead after Pass1, and Pass1 globally precedes the reduce barrier),
// removing the separate x-publish barrier: 2 barriers per step.
// Weight state fully unrolled (registers cannot be dynamically indexed).
// ---------------------------------------------------------------------------
__global__ void __launch_bounds__(64, 4) srwm_scan(
    const float* __restrict__ hin,   // (T, B, 1024)
    const float* __restrict__ Wy0,   // (1, 16, 64, 64)
    const float* __restrict__ Wq0,
    const float* __restrict__ Wk0,
    const float* __restrict__ wb0)   // (1, 16, 64, 4)
{
  const int unit = blockIdx.x;          // 0..511
  const int b    = unit >> 4;
  const int hd   = unit & 15;
  const int tid  = threadIdx.x;         // output row o
  const int lane = tid & 31;
  const int warp = tid >> 5;

  __shared__ __align__(8) float x_s[DH];
  __shared__ __align__(8) float d_s[DH];   // q - k
  __shared__ __align__(8) float k_s[DH];
  __shared__ float redB[14];   // 7 vals x 2 warps
  __shared__ float redC[8];    // 4 vals x 2 warps

  u64 wy2[DH/2], wq2[DH/2], wk2[DH/2];
  float wbr[4];

  // Load initial weights (indexed by head only) — FULL unroll (registers)
  {
    const float4* py = (const float4*)(Wy0 + (size_t)(hd * DH + tid) * DH);
    const float4* pq = (const float4*)(Wq0 + (size_t)(hd * DH + tid) * DH);
    const float4* pk = (const float4*)(Wk0 + (size_t)(hd * DH + tid) * DH);
    #pragma unroll
    for (int c = 0; c < DH / 4; c++) {
      float4 vy = py[c];
      wy2[2*c]   = pack2(vy.x, vy.y);
      wy2[2*c+1] = pack2(vy.z, vy.w);
      float4 vq = pq[c];
      wq2[2*c]   = pack2(vq.x, vq.y);
      wq2[2*c+1] = pack2(vq.z, vq.w);
      float4 vk = pk[c];
      wk2[2*c]   = pack2(vk.x, vk.y);
      wk2[2*c+1] = pack2(vk.z, vk.w);
    }
    float4 vb = *(const float4*)(wb0 + (size_t)(hd * DH + tid) * 4);
    wbr[0] = vb.x; wbr[1] = vb.y; wbr[2] = vb.z; wbr[3] = vb.w;
  }

  const float* xin = hin + (size_t)b * INDIM + hd * DH;
  __nv_bfloat16* yout = g_ys_bf + (size_t)b * INDIM + hd * DH;
  const size_t TSTEP = (size_t)(BSZ * INDIM);

  const u64* x2 = (const u64*)x_s;
  const u64* d2 = (const u64*)d_s;
  const u64* k2 = (const u64*)k_s;

  // Preload x[0]; prefetch x[1]
  float xcur = xin[tid];
  x_s[tid] = xcur;
  __syncthreads();
  float xn = xin[TSTEP + tid];

  for (int t = 0; t < SLEN; t++) {
    // x_s holds x_t (published at previous step's bar B; t=0 from prologue)

    // Pass 1: y = Wy x, zq = Wq x, zk = Wk x (2-way split chains)
    u64 aY0 = 0, aY1 = 0, aQ0 = 0, aQ1 = 0, aK0 = 0, aK1 = 0;
    #pragma unroll
    for (int d = 0; d < DH/4; d++) {
      u64 x0 = x2[2*d], x1 = x2[2*d+1];
      aY0 = fma2(wy2[2*d], x0, aY0);  aY1 = fma2(wy2[2*d+1], x1, aY1);
      aQ0 = fma2(wq2[2*d], x0, aQ0);  aQ1 = fma2(wq2[2*d+1], x1, aQ1);
      aK0 = fma2(wk2[2*d], x0, aK0);  aK1 = fma2(wk2[2*d+1], x1, aK1);
    }
    float yl, yh, ql, qh, kl, kh, t0, t1;
    unpack2(aY0, yl, yh); unpack2(aY1, t0, t1); yl += t0; yh += t1;
    unpack2(aQ0, ql, qh); unpack2(aQ1, t0, t1); ql += t0; qh += t1;
    unpack2(aK0, kl, kh); unpack2(aK1, t0, t1); kl += t0; kh += t1;
    float xo = xcur;   // own x from register

    // exp without max shift (softmax is shift-invariant; logits are O(10))
    float eq = __expf(ql + qh);
    float ek = __expf(kl + kh);
    float ey = __expf(yl + yh);

    // exp sums + beta logits (wb^T x)
    float r7[7] = {eq, ek, ey, wbr[0]*xo, wbr[1]*xo, wbr[2]*xo, wbr[3]*xo};
    reduce64_sum<7>(r7, redB, warp, lane);             // bar A

    float qv   = __fdividef(eq, r7[0]);
    float kv   = __fdividef(ek, r7[1]);
    float outv = __fdividef(ey, r7[2]);
    float beta0 = 1.f / (1.f + __expf(-r7[3]));
    float beta1 = 1.f / (1.f + __expf(-r7[4]));
    float beta2 = 1.f / (1.f + __expf(-r7[5]));
    float beta3 = 1.f / (1.f + __expf(-r7[6]));

    float dv = qv - kv;

    // r8 = wb^T d (4 values) — butterfly BEFORE the publish barrier
    float r8[4] = {wbr[0]*dv, wbr[1]*dv, wbr[2]*dv, wbr[3]*dv};
    #pragma unroll
    for (int off = 16; off > 0; off >>= 1) {
      #pragma unroll
      for (int i = 0; i < 4; i++)
        r8[i] += __shfl_xor_sync(0xffffffffu, r8[i], off);
    }
    if (lane == 0) {
      #pragma unroll
      for (int i = 0; i < 4; i++) redC[warp * 4 + i] = r8[i];
    }

    d_s[tid] = dv;
    k_s[tid] = kv;
    yout[(size_t)t * TSTEP + tid] = __float2bfloat16(outv);
    x_s[tid] = xn;                 // publish x_{t+1}; x_s dead since Pass1
    __syncthreads();                                   // bar B

    // Pass 2: ONLY W·d (2-way split chains)
    u64 aYD0 = 0, aYD1 = 0, aQD0 = 0, aQD1 = 0, aKD0 = 0, aKD1 = 0;
    #pragma unroll
    for (int d = 0; d < DH/4; d++) {
      u64 d0 = d2[2*d], d1 = d2[2*d+1];
      aYD0 = fma2(wy2[2*d], d0, aYD0);  aYD1 = fma2(wy2[2*d+1], d1, aYD1);
      aQD0 = fma2(wq2[2*d], d0, aQD0);  aQD1 = fma2(wq2[2*d+1], d1, aQD1);
      aKD0 = fma2(wk2[2*d], d0, aKD0);  aKD1 = fma2(wk2[2*d+1], d1, aKD1);
    }
    float u0, u1, v0, v1;
    unpack2(aYD0, u0, u1); unpack2(aYD1, v0, v1); float syd = (u0+v0) + (u1+v1);
    unpack2(aQD0, u0, u1); unpack2(aQD1, v0, v1); float sqd = (u0+v0) + (u1+v1);
    unpack2(aKD0, u0, u1); unpack2(aKD1, v0, v1); float skd = (u0+v0) + (u1+v1);

    // finalize r8 (true sums)
    float r8f[4];
    #pragma unroll
    for (int i = 0; i < 4; i++) r8f[i] = redC[i] + redC[4 + i];

    // Rank-1 delta-rule updates (FULL unroll — keeps weights in registers)
    float cy = beta0 * syd;
    float cq = beta1 * sqd;
    float ck = beta2 * skd;
    u64 cy2 = pack2(cy, cy);
    u64 cq2 = pack2(cq, cq);
    u64 ck2 = pack2(ck, ck);
    #pragma unroll
    for (int d = 0; d < DH/2; d++) {
      u64 kd = k2[d];
      wy2[d] = fma2(cy2, kd, wy2[d]);
      wq2[d] = fma2(cq2, kd, wq2[d]);
      wk2[d] = fma2(ck2, kd, wk2[d]);
    }
    float bko = beta3 * kv;
    wbr[0] = fmaf(bko, r8f[0], wbr[0]);
    wbr[1] = fmaf(bko, r8f[1], wbr[1]);
    wbr[2] = fmaf(bko, r8f[2], wbr[2]);
    wbr[3] = fmaf(bko, r8f[3], wbr[3]);

    // rotate x registers; prefetch x[t+2] (a full step of latency cover)
    xcur = xn;
    if (t + 2 < SLEN) xn = xin[(size_t)(t + 2) * TSTEP + tid];
  }
}

// ---------------------------------------------------------------------------
// LayerNorm row statistics for h (32768 rows of 1024)
// ---------------------------------------------------------------------------
__global__ void __launch_bounds__(256) ln_stats_kernel(const float* __restrict__ hin)
{
  const int row  = blockIdx.x;
  const int tid  = threadIdx.x;
  const int lane = tid & 31;
  const int warp = tid >> 5;

  float4 v = *(const float4*)(hin + (size_t)row * INDIM + tid * 4);
  float s  = v.x + v.y + v.z + v.w;
  float s2 = v.x * v.x + v.y * v.y + v.z * v.z + v.w * v.w;

  #pragma unroll
  for (int off = 16; off > 0; off >>= 1) {
    s  += __shfl_xor_sync(0xffffffffu, s, off);
    s2 += __shfl_xor_sync(0xffffffffu, s2, off);
  }
  __shared__ float sa[8], sb[8];
  if (lane == 0) { sa[warp] = s; sb[warp] = s2; }
  __syncthreads();
  if (tid == 0) {
    float S = 0.f, S2 = 0.f;
    #pragma unroll
    for (int i = 0; i < 8; i++) { S += sa[i]; S2 += sb[i]; }
    float m   = S * (1.f / INDIM);
    float var = S2 * (1.f / INDIM) - m * m;
    g_mu[row]   = m;
    g_rstd[row] = rsqrtf(var + 1e-5f);
  }
}

// ---------------------------------------------------------------------------
// out_w fp32 -> bf16
// ---------------------------------------------------------------------------
__global__ void __launch_bounds__(256) convert_w_kernel(const float* __restrict__ w)
{
  int i = blockIdx.x * 256 + threadIdx.x;       // each handles 4 elems
  float4 v = ((const float4*)w)[i];
  __nv_bfloat162* o = (__nv_bfloat162*)g_wb16;
  o[2*i]   = __nv_bfloat162(__float2bfloat16(v.x), __float2bfloat16(v.y));
  o[2*i+1] = __nv_bfloat162(__float2bfloat16(v.z), __float2bfloat16(v.w));
}

// ---------------------------------------------------------------------------
// bf16 tensor-core GEMM helpers (plain functions only — no macros/lambdas)
// ---------------------------------------------------------------------------
__device__ __forceinline__ void cp_async16(unsigned int saddr, const void* gptr) {
  asm volatile("cp.async.cg.shared.global [%0], [%1], 16;\n" :: "r"(saddr), "l"(gptr));
}
__device__ __forceinline__ void cp_commit() {
  asm volatile("cp.async.commit_group;\n");
}
__device__ __forceinline__ void cp_wait0() {
  asm volatile("cp.async.wait_group 0;\n");
}
__device__ __forceinline__ void ldsm4(unsigned int& r0, unsigned int& r1,
                                      unsigned int& r2, unsigned int& r3,
                                      unsigned int addr) {
  asm volatile("ldmatrix.sync.aligned.m8n8.x4.shared.b16 {%0,%1,%2,%3}, [%4];"
               : "=r"(r0), "=r"(r1), "=r"(r2), "=r"(r3) : "r"(addr));
}
__device__ __forceinline__ void mma_bf16(float* c, unsigned int a0, unsigned int a1,
                                         unsigned int a2, unsigned int a3,
                                         unsigned int b0, unsigned int b1) {
  asm volatile(
    "mma.sync.aligned.m16n8k16.row.col.f32.bf16.bf16.f32 "
    "{%0,%1,%2,%3}, {%4,%5,%6,%7}, {%8,%9}, {%0,%1,%2,%3};"
    : "+f"(c[0]), "+f"(c[1]), "+f"(c[2]), "+f"(c[3])
    : "r"(a0), "r"(a1), "r"(a2), "r"(a3), "r"(b0), "r"(b1));
}

#define GBM 128
#define GBN 128
#define GBK 32
#define TSTRIDE 40   // bf16 elems per smem row: 80B stride, conflict-free

// Loads one 128x32 bf16 tile of A and B into the given smem buffers.
__device__ __forceinline__ void load_tile_fn(
    unsigned int sAbuf, unsigned int sBbuf,
    const __nv_bfloat16* Aptr, const __nv_bfloat16* Bptr,
    int m0, int n0, int k0, int tid)
{
  #pragma unroll
  for (int i = 0; i < 2; i++) {
    int c   = tid + i * 256;
    int row = c >> 2;
    int seg = c & 3;
    unsigned int soff = (unsigned int)(row * TSTRIDE + seg * 8) * 2;
    cp_async16(sAbuf + soff, Aptr + (size_t)(m0 + row) * INDIM + k0 + seg * 8);
    cp_async16(sBbuf + soff, Bptr + (size_t)(n0 + row) * INDIM + k0 + seg * 8);
  }
}

// One-barrier-per-iter pipeline: wait(kt) -> bar -> issue load(kt+1) ->
// compute(kt). load(kt+1) lands after the bar so no warp can still be
// reading the buffer it recycles, and it gets the full compute window.
__global__ void __launch_bounds__(256, 2) gemm_bf16_ln(
    const float* __restrict__ hin,
    const float* __restrict__ gvec,
    const float* __restrict__ bvec,
    float* __restrict__ out)
{
  __shared__ __nv_bfloat16 As[2][GBM * TSTRIDE];
  __shared__ __nv_bfloat16 Bs[2][GBN * TSTRIDE];

  const int m0  = blockIdx.y * GBM;
  const int n0  = blockIdx.x * GBN;
  const int tid = threadIdx.x;
  const int lane = tid & 31;
  const int warp = tid >> 5;
  const int wm = warp >> 2;       // 0..1
  const int wn = warp & 3;        // 0..3

  const __nv_bfloat16* Abf = g_ys_bf;
  const __nv_bfloat16* Bbf = g_wb16;

  unsigned int sA0 = (unsigned int)__cvta_generic_to_shared(&As[0][0]);
  unsigned int sA1 = (unsigned int)__cvta_generic_to_shared(&As[1][0]);
  unsigned int sB0 = (unsigned int)__cvta_generic_to_shared(&Bs[0][0]);
  unsigned int sB1 = (unsigned int)__cvta_generic_to_shared(&Bs[1][0]);

  float acc[4][4][4];
  #pragma unroll
  for (int i = 0; i < 4; i++)
    #pragma unroll
    for (int j = 0; j < 4; j++)
      #pragma unroll
      for (int r = 0; r < 4; r++) acc[i][j][r] = 0.f;

  load_tile_fn(sA0, sB0, Abf, Bbf, m0, n0, 0, tid);
  cp_commit();

  const int NKT = INDIM / GBK;   // 32
  for (int kt = 0; kt < NKT; kt++) {
    cp_wait0();                 // tile kt resident
    __syncthreads();            // all warps done with tile kt-1's buffer

    if (kt + 1 < NKT) {
      unsigned int sAn = ((kt + 1) & 1) ? sA1 : sA0;
      unsigned int sBn = ((kt + 1) & 1) ? sB1 : sB0;
      load_tile_fn(sAn, sBn, Abf, Bbf, m0, n0, (kt + 1) * GBK, tid);
      cp_commit();
    }

    unsigned int sAc = (kt & 1) ? sA1 : sA0;
    unsigned int sBc = (kt & 1) ? sB1 : sB0;

    #pragma unroll
    for (int ks = 0; ks < 2; ks++) {
      int koff = ks * 16;
      unsigned int a[4][4];
      #pragma unroll
      for (int mt = 0; mt < 4; mt++) {
        int row = wm * 64 + mt * 16 + (lane & 15);
        int col = koff + 8 * (lane >> 4);
        ldsm4(a[mt][0], a[mt][1], a[mt][2], a[mt][3],
              sAc + (unsigned int)(row * TSTRIDE + col) * 2);
      }
      unsigned int bfrag[4][2];
      #pragma unroll
      for (int half = 0; half < 2; half++) {
        int row = wn * 32 + half * 16 + (lane & 15);
        int col = koff + 8 * (lane >> 4);
        unsigned int r0, r1, r2, r3;
        ldsm4(r0, r1, r2, r3, sBc + (unsigned int)(row * TSTRIDE + col) * 2);
        bfrag[half*2+0][0] = r0; bfrag[half*2+0][1] = r2;
        bfrag[half*2+1][0] = r1; bfrag[half*2+1][1] = r3;
      }
      #pragma unroll
      for (int mt = 0; mt < 4; mt++)
        #pragma unroll
        for (int nt = 0; nt < 4; nt++)
          mma_bf16(acc[mt][nt], a[mt][0], a[mt][1], a[mt][2], a[mt][3],
                   bfrag[nt][0], bfrag[nt][1]);
    }
  }

  // Epilogue: add LN(h) residual
  #pragma unroll
  for (int mt = 0; mt < 4; mt++) {
    int mbase = m0 + wm * 64 + mt * 16 + (lane >> 2);
    #pragma unroll
    for (int rr = 0; rr < 2; rr++) {
      int m = mbase + rr * 8;
      float muv = g_mu[m];
      float rs  = g_rstd[m];
      #pragma unroll
      for (int nt = 0; nt < 4; nt++) {
        int n = n0 + wn * 32 + nt * 8 + 2 * (lane & 3);
        float2 hv = *(const float2*)(hin + (size_t)m * INDIM + n);
        float2 gv = *(const float2*)(gvec + n);
        float2 bv = *(const float2*)(bvec + n);
        float2 o;
        o.x = acc[mt][nt][rr*2+0] + (hv.x - muv) * rs * gv.x + bv.x;
        o.y = acc[mt][nt][rr*2+1] + (hv.y - muv) * rs * gv.y + bv.y;
        *(float2*)(out + (size_t)m * INDIM + n) = o;
      }
    }
  }
}

// ---------------------------------------------------------------------------
extern "C" void kernel_launch(void* const* d_in, const int* in_sizes, int n_in,
                              void* d_out, int out_size)
{
  const float* h_in = (const float*)d_in[0];
  const float* W_y  = (const float*)d_in[1];
  const float* W_q  = (const float*)d_in[2];
  const float* W_k  = (const float*)d_in[3];
  const float* w_b  = (const float*)d_in[4];
  const float* outw = (const float*)d_in[5];
  const float* ln_g = (const float*)d_in[6];
  const float* ln_b = (const float*)d_in[7];
  float* out = (float*)d_out;

  // Small independent prep
  convert_w_kernel<<<INDIM * INDIM / 4 / 256, 256>>>(outw);
  ln_stats_kernel<<<MROWS, 256>>>(h_in);

  // Sequential SRWM scan: 512 units, 64 threads each (2 barriers/step)
  srwm_scan<<<BSZ * NH, 64>>>(h_in, W_y, W_q, W_k, w_b);

  // Output GEMM (bf16 tensor cores, 1 barrier/K-iter) + LN residual
  dim3 grid(INDIM / GBN, MROWS / GBM);
  gemm_bf16_ln<<<grid, 256>>>(h_in, ln_g, ln_b, out);
}

// round 17
// speedup vs baseline: 1.0530x; 1.0530x over previous
#include <cuda_runtime.h>
#include <cuda_bf16.h>
#include <math.h>

// Problem dims
#define SLEN 1024
#define BSZ  32
#define NH   16
#define DH   64
#define INDIM 1024            // NH*DH
#define MROWS (SLEN*BSZ)      // 32768

typedef unsigned long long u64;

// Scratch (device globals; no allocation allowed)
__device__ __nv_bfloat16 g_ys_bf[(size_t)MROWS * INDIM];   // scan output, bf16
__device__ __nv_bfloat16 g_wb16[(size_t)INDIM * INDIM];    // out_w in bf16
__device__ float g_mu[MROWS];
__device__ float g_rstd[MROWS];

// ---------------------------------------------------------------------------
// packed f32x2 helpers
// ---------------------------------------------------------------------------
__device__ __forceinline__ u64 pack2(float lo, float hi) {
  u64 r; asm("mov.b64 %0, {%1, %2};" : "=l"(r) : "f"(lo), "f"(hi)); return r;
}
__device__ __forceinline__ void unpack2(u64 v, float& lo, float& hi) {
  asm("mov.b64 {%0, %1}, %2;" : "=f"(lo), "=f"(hi) : "l"(v));
}
__device__ __forceinline__ u64 fma2(u64 a, u64 b, u64 c) {
  u64 d; asm("fma.rn.f32x2 %0, %1, %2, %3;" : "=l"(d) : "l"(a), "l"(b), "l"(c));
  return d;
}

// ---------------------------------------------------------------------------
// 64-thread (2-warp) SUM reduction, N values, ONE barrier.
// ---------------------------------------------------------------------------
template<int N>
__device__ __forceinline__ void reduce64_sum(float* v, float* red, int warp, int lane) {
  #pragma unroll
  for (int off = 16; off > 0; off >>= 1) {
    #pragma unroll
    for (int i = 0; i < N; i++)
      v[i] += __shfl_xor_sync(0xffffffffu, v[i], off);
  }
  if (lane == 0) {
    #pragma unroll
    for (int i = 0; i < N; i++) red[warp * N + i] = v[i];
  }
  __syncthreads();
  #pragma unroll
  for (int i = 0; i < N; i++)
    v[i] = red[i] + red[N + i];
}

// ---------------------------------------------------------------------------
// SRWM sequential scan — EXACT R9 configuration (best measured: 2053us total).
// 512 CTAs x 64 threads, d = q-k trick, 3 barriers/step, full unrolls.
// ---------------------------------------------------------------------------
__global__ void __launch_bounds__(64, 4) srwm_scan(
    const float* __restrict__ hin,   // (T, B, 1024)
    const float* __restrict__ Wy0,   // (1, 16, 64, 64)
    const float* __restrict__ Wq0,
    const float* __restrict__ Wk0,
    const float* __restrict__ wb0)   // (1, 16, 64, 4)
{
  const int unit = blockIdx.x;          // 0..511
  const int b    = unit >> 4;
  const int hd   = unit & 15;
  const int tid  = threadIdx.x;         // output row o
  const int lane = tid & 31;
  const int warp = tid >> 5;

  __shared__ __align__(8) float x_s[DH];
  __shared__ __align__(8) float d_s[DH];   // q - k
  __shared__ __align__(8) float k_s[DH];
  __shared__ float redB[14];   // 7 vals x 2 warps
  __shared__ float redC[8];    // 4 vals x 2 warps

  u64 wy2[DH/2], wq2[DH/2], wk2[DH/2];
  float wbr[4];

  // Load initial weights (indexed by head only)
  {
    const float4* py = (const float4*)(Wy0 + (size_t)(hd * DH + tid) * DH);
    const float4* pq = (const float4*)(Wq0 + (size_t)(hd * DH + tid) * DH);
    const float4* pk = (const float4*)(Wk0 + (size_t)(hd * DH + tid) * DH);
    #pragma unroll
    for (int c = 0; c < DH / 4; c++) {
      float4 vy = py[c];
      wy2[2*c]   = pack2(vy.x, vy.y);
      wy2[2*c+1] = pack2(vy.z, vy.w);
      float4 vq = pq[c];
      wq2[2*c]   = pack2(vq.x, vq.y);
      wq2[2*c+1] = pack2(vq.z, vq.w);
      float4 vk = pk[c];
      wk2[2*c]   = pack2(vk.x, vk.y);
      wk2[2*c+1] = pack2(vk.z, vk.w);
    }
    float4 vb = *(const float4*)(wb0 + (size_t)(hd * DH + tid) * 4);
    wbr[0] = vb.x; wbr[1] = vb.y; wbr[2] = vb.z; wbr[3] = vb.w;
  }

  const float* xin = hin + (size_t)b * INDIM + hd * DH;
  __nv_bfloat16* yout = g_ys_bf + (size_t)b * INDIM + hd * DH;

  const u64* x2 = (const u64*)x_s;
  const u64* d2 = (const u64*)d_s;
  const u64* k2 = (const u64*)k_s;

  // Prefetch x for t=0
  float xn = xin[tid];

  for (int t = 0; t < SLEN; t++) {
    x_s[tid] = xn;
    __syncthreads();                                   // bar 1

    // Prefetch next step's x; memory latency overlaps this whole step.
    if (t + 1 < SLEN) xn = xin[(size_t)(t + 1) * (BSZ * INDIM) + tid];

    // Pass 1: y = Wy x, zq = Wq x, zk = Wk x (2-way split chains)
    u64 aY0 = 0, aY1 = 0, aQ0 = 0, aQ1 = 0, aK0 = 0, aK1 = 0;
    #pragma unroll
    for (int d = 0; d < DH/4; d++) {
      u64 x0 = x2[2*d], x1 = x2[2*d+1];
      aY0 = fma2(wy2[2*d], x0, aY0);  aY1 = fma2(wy2[2*d+1], x1, aY1);
      aQ0 = fma2(wq2[2*d], x0, aQ0);  aQ1 = fma2(wq2[2*d+1], x1, aQ1);
      aK0 = fma2(wk2[2*d], x0, aK0);  aK1 = fma2(wk2[2*d+1], x1, aK1);
    }
    float yl, yh, ql, qh, kl, kh, t0, t1;
    unpack2(aY0, yl, yh); unpack2(aY1, t0, t1); yl += t0; yh += t1;
    unpack2(aQ0, ql, qh); unpack2(aQ1, t0, t1); ql += t0; qh += t1;
    unpack2(aK0, kl, kh); unpack2(aK1, t0, t1); kl += t0; kh += t1;
    float xo = x_s[tid];

    // exp without max shift (softmax is shift-invariant; logits are O(10))
    float eq = __expf(ql + qh);
    float ek = __expf(kl + kh);
    float ey = __expf(yl + yh);

    // exp sums + beta logits (wb^T x)
    float r7[7] = {eq, ek, ey, wbr[0]*xo, wbr[1]*xo, wbr[2]*xo, wbr[3]*xo};
    reduce64_sum<7>(r7, redB, warp, lane);             // bar 2

    float qv   = __fdividef(eq, r7[0]);
    float kv   = __fdividef(ek, r7[1]);
    float outv = __fdividef(ey, r7[2]);
    float beta0 = 1.f / (1.f + __expf(-r7[3]));
    float beta1 = 1.f / (1.f + __expf(-r7[4]));
    float beta2 = 1.f / (1.f + __expf(-r7[5]));
    float beta3 = 1.f / (1.f + __expf(-r7[6]));

    float dv = qv - kv;

    // r8 = wb^T d (4 values) — butterfly BEFORE the publish barrier
    float r8[4] = {wbr[0]*dv, wbr[1]*dv, wbr[2]*dv, wbr[3]*dv};
    #pragma unroll
    for (int off = 16; off > 0; off >>= 1) {
      #pragma unroll
      for (int i = 0; i < 4; i++)
        r8[i] += __shfl_xor_sync(0xffffffffu, r8[i], off);
    }
    if (lane == 0) {
      #pragma unroll
      for (int i = 0; i < 4; i++) redC[warp * 4 + i] = r8[i];
    }

    d_s[tid] = dv;
    k_s[tid] = kv;
    yout[(size_t)t * (BSZ * INDIM) + tid] = __float2bfloat16(outv);
    __syncthreads();                                   // bar 3

    // Pass 2: ONLY W·d (2-way split chains)
    u64 aYD0 = 0, aYD1 = 0, aQD0 = 0, aQD1 = 0, aKD0 = 0, aKD1 = 0;
    #pragma unroll
    for (int d = 0; d < DH/4; d++) {
      u64 d0 = d2[2*d], d1 = d2[2*d+1];
      aYD0 = fma2(wy2[2*d], d0, aYD0);  aYD1 = fma2(wy2[2*d+1], d1, aYD1);
      aQD0 = fma2(wq2[2*d], d0, aQD0);  aQD1 = fma2(wq2[2*d+1], d1, aQD1);
      aKD0 = fma2(wk2[2*d], d0, aKD0);  aKD1 = fma2(wk2[2*d+1], d1, aKD1);
    }
    float u0, u1, v0, v1;
    unpack2(aYD0, u0, u1); unpack2(aYD1, v0, v1); float syd = (u0+v0) + (u1+v1);
    unpack2(aQD0, u0, u1); unpack2(aQD1, v0, v1); float sqd = (u0+v0) + (u1+v1);
    unpack2(aKD0, u0, u1); unpack2(aKD1, v0, v1); float skd = (u0+v0) + (u1+v1);

    // finalize r8 (true sums)
    float r8f[4];
    #pragma unroll
    for (int i = 0; i < 4; i++) r8f[i] = redC[i] + redC[4 + i];

    // Rank-1 delta-rule updates
    float cy = beta0 * syd;
    float cq = beta1 * sqd;
    float ck = beta2 * skd;
    u64 cy2 = pack2(cy, cy);
    u64 cq2 = pack2(cq, cq);
    u64 ck2 = pack2(ck, ck);
    #pragma unroll
    for (int d = 0; d < DH/2; d++) {
      u64 kd = k2[d];
      wy2[d] = fma2(cy2, kd, wy2[d]);
      wq2[d] = fma2(cq2, kd, wq2[d]);
      wk2[d] = fma2(ck2, kd, wk2[d]);
    }
    float bko = beta3 * kv;
    #pragma unroll
    for (int j = 0; j < 4; j++)
      wbr[j] = fmaf(bko, r8f[j], wbr[j]);
  }
}

// ---------------------------------------------------------------------------
// LayerNorm row statistics for h (32768 rows of 1024)
// ---------------------------------------------------------------------------
__global__ void __launch_bounds__(256) ln_stats_kernel(const float* __restrict__ hin)
{
  const int row  = blockIdx.x;
  const int tid  = threadIdx.x;
  const int lane = tid & 31;
  const int warp = tid >> 5;

  float4 v = *(const float4*)(hin + (size_t)row * INDIM + tid * 4);
  float s  = v.x + v.y + v.z + v.w;
  float s2 = v.x * v.x + v.y * v.y + v.z * v.z + v.w * v.w;

  #pragma unroll
  for (int off = 16; off > 0; off >>= 1) {
    s  += __shfl_xor_sync(0xffffffffu, s, off);
    s2 += __shfl_xor_sync(0xffffffffu, s2, off);
  }
  __shared__ float sa[8], sb[8];
  if (lane == 0) { sa[warp] = s; sb[warp] = s2; }
  __syncthreads();
  if (tid == 0) {
    float S = 0.f, S2 = 0.f;
    #pragma unroll
    for (int i = 0; i < 8; i++) { S += sa[i]; S2 += sb[i]; }
    float m   = S * (1.f / INDIM);
    float var = S2 * (1.f / INDIM) - m * m;
    g_mu[row]   = m;
    g_rstd[row] = rsqrtf(var + 1e-5f);
  }
}

// ---------------------------------------------------------------------------
// out_w fp32 -> bf16
// ---------------------------------------------------------------------------
__global__ void __launch_bounds__(256) convert_w_kernel(const float* __restrict__ w)
{
  int i = blockIdx.x * 256 + threadIdx.x;       // each handles 4 elems
  float4 v = ((const float4*)w)[i];
  __nv_bfloat162* o = (__nv_bfloat162*)g_wb16;
  o[2*i]   = __nv_bfloat162(__float2bfloat16(v.x), __float2bfloat16(v.y));
  o[2*i+1] = __nv_bfloat162(__float2bfloat16(v.z), __float2bfloat16(v.w));
}

// ---------------------------------------------------------------------------
// bf16 tensor-core GEMM helpers (plain functions only — no macros/lambdas)
// ---------------------------------------------------------------------------
__device__ __forceinline__ void cp_async16(unsigned int saddr, const void* gptr) {
  asm volatile("cp.async.cg.shared.global [%0], [%1], 16;\n" :: "r"(saddr), "l"(gptr));
}
__device__ __forceinline__ void cp_commit() {
  asm volatile("cp.async.commit_group;\n");
}
__device__ __forceinline__ void cp_wait0() {
  asm volatile("cp.async.wait_group 0;\n");
}
__device__ __forceinline__ void ldsm4(unsigned int& r0, unsigned int& r1,
                                      unsigned int& r2, unsigned int& r3,
                                      unsigned int addr) {
  asm volatile("ldmatrix.sync.aligned.m8n8.x4.shared.b16 {%0,%1,%2,%3}, [%4];"
               : "=r"(r0), "=r"(r1), "=r"(r2), "=r"(r3) : "r"(addr));
}
__device__ __forceinline__ void mma_bf16(float* c, unsigned int a0, unsigned int a1,
                                         unsigned int a2, unsigned int a3,
                                         unsigned int b0, unsigned int b1) {
  asm volatile(
    "mma.sync.aligned.m16n8k16.row.col.f32.bf16.bf16.f32 "
    "{%0,%1,%2,%3}, {%4,%5,%6,%7}, {%8,%9}, {%0,%1,%2,%3};"
    : "+f"(c[0]), "+f"(c[1]), "+f"(c[2]), "+f"(c[3])
    : "r"(a0), "r"(a1), "r"(a2), "r"(a3), "r"(b0), "r"(b1));
}

#define GBM 128
#define GBN 128
#define GBK 64
#define TSTRIDE 72   // bf16 elems per smem row: 144B stride (64 + 8 pad)
#define TILE_ELEMS (GBM * TSTRIDE)               // 9216 bf16 per operand tile
#define SMEM_DYN (4 * TILE_ELEMS * 2)            // A0,A1,B0,B1 = 73728 bytes

// Loads one 128x64 bf16 tile of A and B (4 chunks/thread/operand).
__device__ __forceinline__ void load_tile_fn(
    unsigned int sAbuf, unsigned int sBbuf,
    const __nv_bfloat16* Aptr, const __nv_bfloat16* Bptr,
    int m0, int n0, int k0, int tid)
{
  #pragma unroll
  for (int i = 0; i < 4; i++) {
    int c   = tid + i * 256;       // 0..1023
    int row = c >> 3;              // 0..127
    int seg = c & 7;               // 0..7 (8 bf16 each)
    unsigned int soff = (unsigned int)(row * TSTRIDE + seg * 8) * 2;
    cp_async16(sAbuf + soff, Aptr + (size_t)(m0 + row) * INDIM + k0 + seg * 8);
    cp_async16(sBbuf + soff, Bptr + (size_t)(n0 + row) * INDIM + k0 + seg * 8);
  }
}

// One-barrier-per-iter pipeline, GBK=64 (16 K-iterations).
__global__ void __launch_bounds__(256, 2) gemm_bf16_ln(
    const float* __restrict__ hin,
    const float* __restrict__ gvec,
    const float* __restrict__ bvec,
    float* __restrict__ out)
{
  extern __shared__ __nv_bfloat16 smem_dyn[];

  const int m0  = blockIdx.y * GBM;
  const int n0  = blockIdx.x * GBN;
  const int tid = threadIdx.x;
  const int lane = tid & 31;
  const int warp = tid >> 5;
  const int wm = warp >> 2;       // 0..1
  const int wn = warp & 3;        // 0..3

  const __nv_bfloat16* Abf = g_ys_bf;
  const __nv_bfloat16* Bbf = g_wb16;

  unsigned int base = (unsigned int)__cvta_generic_to_shared(smem_dyn);
  unsigned int sA0 = base;
  unsigned int sA1 = base + TILE_ELEMS * 2;
  unsigned int sB0 = base + 2 * TILE_ELEMS * 2;
  unsigned int sB1 = base + 3 * TILE_ELEMS * 2;

  float acc[4][4][4];
  #pragma unroll
  for (int i = 0; i < 4; i++)
    #pragma unroll
    for (int j = 0; j < 4; j++)
      #pragma unroll
      for (int r = 0; r < 4; r++) acc[i][j][r] = 0.f;

  load_tile_fn(sA0, sB0, Abf, Bbf, m0, n0, 0, tid);
  cp_commit();

  const int NKT = INDIM / GBK;   // 16
  for (int kt = 0; kt < NKT; kt++) {
    cp_wait0();                 // tile kt resident
    __syncthreads();            // all warps done with the recycled buffer

    if (kt + 1 < NKT) {
      unsigned int sAn = ((kt + 1) & 1) ? sA1 : sA0;
      unsigned int sBn = ((kt + 1) & 1) ? sB1 : sB0;
      load_tile_fn(sAn, sBn, Abf, Bbf, m0, n0, (kt + 1) * GBK, tid);
      cp_commit();
    }

    unsigned int sAc = (kt & 1) ? sA1 : sA0;
    unsigned int sBc = (kt & 1) ? sB1 : sB0;

    #pragma unroll
    for (int ks = 0; ks < 4; ks++) {
      int koff = ks * 16;
      unsigned int a[4][4];
      #pragma unroll
      for (int mt = 0; mt < 4; mt++) {
        int row = wm * 64 + mt * 16 + (lane & 15);
        int col = koff + 8 * (lane >> 4);
        ldsm4(a[mt][0], a[mt][1], a[mt][2], a[mt][3],
              sAc + (unsigned int)(row * TSTRIDE + col) * 2);
      }
      unsigned int bfrag[4][2];
      #pragma unroll
      for (int half = 0; half < 2; half++) {
        int row = wn * 32 + half * 16 + (lane & 15);
        int col = koff + 8 * (lane >> 4);
        unsigned int r0, r1, r2, r3;
        ldsm4(r0, r1, r2, r3, sBc + (unsigned int)(row * TSTRIDE + col) * 2);
        bfrag[half*2+0][0] = r0; bfrag[half*2+0][1] = r2;
        bfrag[half*2+1][0] = r1; bfrag[half*2+1][1] = r3;
      }
      #pragma unroll
      for (int mt = 0; mt < 4; mt++)
        #pragma unroll
        for (int nt = 0; nt < 4; nt++)
          mma_bf16(acc[mt][nt], a[mt][0], a[mt][1], a[mt][2], a[mt][3],
                   bfrag[nt][0], bfrag[nt][1]);
    }
  }

  // Epilogue: add LN(h) residual
  #pragma unroll
  for (int mt = 0; mt < 4; mt++) {
    int mbase = m0 + wm * 64 + mt * 16 + (lane >> 2);
    #pragma unroll
    for (int rr = 0; rr < 2; rr++) {
      int m = mbase + rr * 8;
      float muv = g_mu[m];
      float rs  = g_rstd[m];
      #pragma unroll
      for (int nt = 0; nt < 4; nt++) {
        int n = n0 + wn * 32 + nt * 8 + 2 * (lane & 3);
        float2 hv = *(const float2*)(hin + (size_t)m * INDIM + n);
        float2 gv = *(const float2*)(gvec + n);
        float2 bv = *(const float2*)(bvec + n);
        float2 o;
        o.x = acc[mt][nt][rr*2+0] + (hv.x - muv) * rs * gv.x + bv.x;
        o.y = acc[mt][nt][rr*2+1] + (hv.y - muv) * rs * gv.y + bv.y;
        *(float2*)(out + (size_t)m * INDIM + n) = o;
      }
    }
  }
}

// ---------------------------------------------------------------------------
extern "C" void kernel_launch(void* const* d_in, const int* in_sizes, int n_in,
                              void* d_out, int out_size)
{
  const float* h_in = (const float*)d_in[0];
  const float* W_y  = (const float*)d_in[1];
  const float* W_q  = (const float*)d_in[2];
  const float* W_k  = (const float*)d_in[3];
  const float* w_b  = (const float*)d_in[4];
  const float* outw = (const float*)d_in[5];
  const float* ln_g = (const float*)d_in[6];
  const float* ln_b = (const float*)d_in[7];
  float* out = (float*)d_out;

  // Allow 72KB dynamic smem for the GEMM (host attribute set; no allocation)
  cudaFuncSetAttribute(gemm_bf16_ln,
                       cudaFuncAttributeMaxDynamicSharedMemorySize, SMEM_DYN);

  // Small independent prep
  convert_w_kernel<<<INDIM * INDIM / 4 / 256, 256>>>(outw);
  ln_stats_kernel<<<MROWS, 256>>>(h_in);

  // Sequential SRWM scan: 512 units, 64 threads each (R9 config)
  srwm_scan<<<BSZ * NH, 64>>>(h_in, W_y, W_q, W_k, w_b);

  // Output GEMM (bf16 tensor cores, GBK=64, 1 barrier/K-iter) + LN residual
  dim3 grid(INDIM / GBN, MROWS / GBM);
  gemm_bf16_ln<<<grid, 256, SMEM_DYN>>>(h_in, ln_g, ln_b, out);
}